// round 1
// baseline (speedup 1.0000x reference)
#include <cuda_runtime.h>
#include <cuda_bf16.h>
#include <mma.h>
#include <cstdint>
#include <cstdio>

using namespace nvcuda;

// Problem dims (fixed)
#define S_    128
#define N_    256
#define H_    1024
#define E_    512
#define V_    32000
#define KE_   1024        // energy channels
#define NH_   (N_*H_)     // 262144
#define RNNK_ (H_+E_)     // 1536
#define G4_   (4*H_)      // 4096

// Scratch (allocation-free: __device__ globals)
__device__ float g_hterm[N_];
__device__ float g_ctx[N_*H_];
__device__ float g_rnn_in[N_*RNNK_];
__device__ float g_gates[N_*G4_];
__device__ float g_h1[N_*H_];

// ---------------------------------------------------------------------------
// hterm[n] = dot(W_energy[K-1, 0:H], h0[n]) + b_energy[K-1]
// one warp per n
// ---------------------------------------------------------------------------
__global__ void hterm_kernel(const float* __restrict__ h0,
                             const float* __restrict__ W_energy,
                             const float* __restrict__ b_energy) {
    int warp = threadIdx.x >> 5, lane = threadIdx.x & 31;
    int n = blockIdx.x * 8 + warp;
    const float* w1 = W_energy + (size_t)(KE_ - 1) * (2 * H_);
    const float* h  = h0 + (size_t)n * H_;
    float acc = 0.f;
    for (int t = lane; t < H_; t += 32) acc = fmaf(h[t], w1[t], acc);
    #pragma unroll
    for (int o = 16; o; o >>= 1) acc += __shfl_xor_sync(0xffffffffu, acc, o);
    if (lane == 0) g_hterm[n] = acc + b_energy[KE_ - 1];
}

// ---------------------------------------------------------------------------
// Fused: energy_last[s,n] = relu(hterm[n] + dot(we2, enc[s,n,:]))
//        attn = softmax over s; ctx[n,:] = sum_s attn[s]*enc[s,n,:]
// one block (256 thr) per n
// ---------------------------------------------------------------------------
__global__ void attn_ctx_kernel(const float* __restrict__ enc,
                                const float* __restrict__ W_energy) {
    int n = blockIdx.x;
    int tid = threadIdx.x;
    int lane = tid & 31, warp = tid >> 5;

    __shared__ float we2[H_];
    __shared__ float e_s[S_];
    __shared__ float attn[S_];
    __shared__ float red[8];

    const float* w2 = W_energy + (size_t)(KE_ - 1) * (2 * H_) + H_;
    for (int j = tid; j < H_; j += 256) we2[j] = w2[j];
    __syncthreads();

    const float* encn = enc + (size_t)n * H_;
    float ht = g_hterm[n];

    // phase 1: energies, warp per s (no block barriers inside)
    for (int s = warp; s < S_; s += 8) {
        const float* row = encn + (size_t)s * NH_;
        float acc = 0.f;
        for (int t = lane; t < H_; t += 32) acc = fmaf(row[t], we2[t], acc);
        #pragma unroll
        for (int o = 16; o; o >>= 1) acc += __shfl_xor_sync(0xffffffffu, acc, o);
        if (lane == 0) e_s[s] = fmaxf(acc + ht, 0.f);
    }
    __syncthreads();

    // softmax over S=128 values
    float v = (tid < S_) ? e_s[tid] : -1e30f;
    float m = v;
    #pragma unroll
    for (int o = 16; o; o >>= 1) m = fmaxf(m, __shfl_xor_sync(0xffffffffu, m, o));
    if (lane == 0) red[warp] = m;
    __syncthreads();
    m = red[0];
    #pragma unroll
    for (int w = 1; w < 8; w++) m = fmaxf(m, red[w]);
    float wv = (tid < S_) ? expf(v - m) : 0.f;
    __syncthreads();                    // done reading red before re-writing
    float sum = wv;
    #pragma unroll
    for (int o = 16; o; o >>= 1) sum += __shfl_xor_sync(0xffffffffu, sum, o);
    if (lane == 0) red[warp] = sum;
    __syncthreads();
    sum = 0.f;
    #pragma unroll
    for (int w = 0; w < 8; w++) sum += red[w];
    if (tid < S_) attn[tid] = wv / sum;
    __syncthreads();

    // phase 2: ctx accumulation, coalesced float4 per thread (1024 = 256*4)
    int j0 = tid * 4;
    float c0 = 0.f, c1 = 0.f, c2 = 0.f, c3 = 0.f;
    for (int s = 0; s < S_; s++) {
        float a = attn[s];
        const float4 r = *reinterpret_cast<const float4*>(encn + (size_t)s * NH_ + j0);
        c0 = fmaf(a, r.x, c0);
        c1 = fmaf(a, r.y, c1);
        c2 = fmaf(a, r.z, c2);
        c3 = fmaf(a, r.w, c3);
    }
    *reinterpret_cast<float4*>(g_ctx + (size_t)n * H_ + j0) = make_float4(c0, c1, c2, c3);
}

// ---------------------------------------------------------------------------
// rnn_in[n, 0:H] = ctx[n]; rnn_in[n, H:H+E] = emb[input[n]]
// ---------------------------------------------------------------------------
__global__ void rnn_in_kernel(const int* __restrict__ input,
                              const float* __restrict__ emb) {
    int idx = blockIdx.x * blockDim.x + threadIdx.x;    // < N_*RNNK_
    int n = idx / RNNK_, c = idx % RNNK_;
    float v;
    if (c < H_) v = g_ctx[(size_t)n * H_ + c];
    else        v = emb[(size_t)input[n] * E_ + (c - H_)];
    g_rnn_in[idx] = v;
}

// ---------------------------------------------------------------------------
// Generic NT GEMM, tf32 tensor cores, fp32 accumulate.
// C[M=256, Nc] (+)= A[256, K] * B[Nc, K]^T
// Block tile 256x64, BK=32. 8 warps: 4(m) x 2(n), warp tile 64x32.
// ---------------------------------------------------------------------------
template <bool ACC>
__global__ void __launch_bounds__(256, 1)
gemm_nt_tf32(const float* __restrict__ A, const float* __restrict__ B,
             float* __restrict__ C, int Nc, int K) {
    constexpr int BM = 256, BN = 64, BK = 32, LDS_ = BK + 4;
    __shared__ float As[BM][LDS_];
    __shared__ float Bs[BN][LDS_];

    int tid  = threadIdx.x;
    int warp = tid >> 5;
    int wm = warp >> 1;          // 0..3
    int wn = warp & 1;           // 0..1
    int bn = blockIdx.x * BN;

    wmma::fragment<wmma::accumulator, 16, 16, 8, float> c[4][2];
    if (ACC) {
        #pragma unroll
        for (int i = 0; i < 4; i++)
            #pragma unroll
            for (int j = 0; j < 2; j++)
                wmma::load_matrix_sync(c[i][j],
                    C + (size_t)(wm * 64 + i * 16) * Nc + bn + wn * 32 + j * 16,
                    Nc, wmma::mem_row_major);
    } else {
        #pragma unroll
        for (int i = 0; i < 4; i++)
            #pragma unroll
            for (int j = 0; j < 2; j++)
                wmma::fill_fragment(c[i][j], 0.f);
    }

    for (int k0 = 0; k0 < K; k0 += BK) {
        // A chunk: 256x32 = 2048 float4, 8 per thread
        #pragma unroll
        for (int i = 0; i < 8; i++) {
            int e = tid + i * 256;
            int r = e >> 3, c4 = e & 7;
            float4 v = *reinterpret_cast<const float4*>(A + (size_t)r * K + k0 + c4 * 4);
            *reinterpret_cast<float4*>(&As[r][c4 * 4]) = v;
        }
        // B chunk: 64x32 = 512 float4, 2 per thread
        #pragma unroll
        for (int i = 0; i < 2; i++) {
            int e = tid + i * 256;
            int r = e >> 3, c4 = e & 7;
            float4 v = *reinterpret_cast<const float4*>(B + (size_t)(bn + r) * K + k0 + c4 * 4);
            *reinterpret_cast<float4*>(&Bs[r][c4 * 4]) = v;
        }
        __syncthreads();

        #pragma unroll
        for (int kk = 0; kk < BK; kk += 8) {
            wmma::fragment<wmma::matrix_a, 16, 16, 8, wmma::precision::tf32, wmma::row_major> a[4];
            wmma::fragment<wmma::matrix_b, 16, 16, 8, wmma::precision::tf32, wmma::col_major> b[2];
            #pragma unroll
            for (int i = 0; i < 4; i++) {
                wmma::load_matrix_sync(a[i], &As[wm * 64 + i * 16][kk], LDS_);
                #pragma unroll
                for (int t = 0; t < a[i].num_elements; t++)
                    a[i].x[t] = wmma::__float_to_tf32(a[i].x[t]);
            }
            #pragma unroll
            for (int j = 0; j < 2; j++) {
                wmma::load_matrix_sync(b[j], &Bs[wn * 32 + j * 16][kk], LDS_);
                #pragma unroll
                for (int t = 0; t < b[j].num_elements; t++)
                    b[j].x[t] = wmma::__float_to_tf32(b[j].x[t]);
            }
            #pragma unroll
            for (int i = 0; i < 4; i++)
                #pragma unroll
                for (int j = 0; j < 2; j++)
                    wmma::mma_sync(c[i][j], a[i], b[j], c[i][j]);
        }
        __syncthreads();
    }

    #pragma unroll
    for (int i = 0; i < 4; i++)
        #pragma unroll
        for (int j = 0; j < 2; j++)
            wmma::store_matrix_sync(
                C + (size_t)(wm * 64 + i * 16) * Nc + bn + wn * 32 + j * 16,
                c[i][j], Nc, wmma::mem_row_major);
}

// ---------------------------------------------------------------------------
// LSTM pointwise: gates (raw) + biases -> h1, c1.  PyTorch gate order i,f,g,o.
// Writes g_h1 (for vocab GEMM) and h1/c1 output regions.
// ---------------------------------------------------------------------------
__global__ void lstm_kernel(const float* __restrict__ cell,
                            const float* __restrict__ b_ih,
                            const float* __restrict__ b_hh,
                            float* __restrict__ out) {
    int idx = blockIdx.x * 256 + threadIdx.x;    // < N_*H_
    int n = idx >> 10, h = idx & 1023;
    const float* g = g_gates + (size_t)n * G4_;
    float xi = g[h]          + b_ih[h]          + b_hh[h];
    float xf = g[H_ + h]     + b_ih[H_ + h]     + b_hh[H_ + h];
    float xg = g[2 * H_ + h] + b_ih[2 * H_ + h] + b_hh[2 * H_ + h];
    float xo = g[3 * H_ + h] + b_ih[3 * H_ + h] + b_hh[3 * H_ + h];
    float si = 1.f / (1.f + expf(-xi));
    float sf = 1.f / (1.f + expf(-xf));
    float so = 1.f / (1.f + expf(-xo));
    float c1 = sf * cell[idx] + si * tanhf(xg);
    float h1 = so * tanhf(c1);
    g_h1[idx] = h1;
    out[(size_t)N_ * V_ + idx] = h1;
    out[(size_t)N_ * V_ + NH_ + idx] = c1;
}

// ---------------------------------------------------------------------------
// predictions += b_fc (broadcast over rows)
// ---------------------------------------------------------------------------
__global__ void bias_pred_kernel(const float* __restrict__ b_fc,
                                 float* __restrict__ pred) {
    int total = N_ * V_ / 4;
    for (int i = blockIdx.x * blockDim.x + threadIdx.x; i < total;
         i += gridDim.x * blockDim.x) {
        float4 p = reinterpret_cast<float4*>(pred)[i];
        int j = (i * 4) % V_;
        p.x += b_fc[j];
        p.y += b_fc[j + 1];
        p.z += b_fc[j + 2];
        p.w += b_fc[j + 3];
        reinterpret_cast<float4*>(pred)[i] = p;
    }
}

// ---------------------------------------------------------------------------
extern "C" void kernel_launch(void* const* d_in, const int* in_sizes, int n_in,
                              void* d_out, int out_size) {
    const int*   input    = (const int*)d_in[0];
    const float* enc      = (const float*)d_in[1];
    const float* hidden   = (const float*)d_in[2];
    const float* cell     = (const float*)d_in[3];
    const float* emb      = (const float*)d_in[4];
    const float* W_energy = (const float*)d_in[5];
    const float* b_energy = (const float*)d_in[6];
    const float* W_ih     = (const float*)d_in[7];
    const float* b_ih     = (const float*)d_in[8];
    const float* W_hh     = (const float*)d_in[9];
    const float* b_hh     = (const float*)d_in[10];
    const float* W_fc     = (const float*)d_in[11];
    const float* b_fc     = (const float*)d_in[12];
    float* out = (float*)d_out;

    void *p_rnn = nullptr, *p_gates = nullptr, *p_h1 = nullptr;
    cudaGetSymbolAddress(&p_rnn, g_rnn_in);
    cudaGetSymbolAddress(&p_gates, g_gates);
    cudaGetSymbolAddress(&p_h1, g_h1);

    hterm_kernel<<<N_ / 8, 256>>>(hidden, W_energy, b_energy);
    attn_ctx_kernel<<<N_, 256>>>(enc, W_energy);
    rnn_in_kernel<<<(N_ * RNNK_) / 256, 256>>>(input, emb);

    // gates = rnn_in @ W_ih^T + h0 @ W_hh^T   (biases folded into lstm_kernel)
    gemm_nt_tf32<false><<<dim3(G4_ / 64, 1), 256>>>(
        (const float*)p_rnn, W_ih, (float*)p_gates, G4_, RNNK_);
    gemm_nt_tf32<true><<<dim3(G4_ / 64, 1), 256>>>(
        hidden, W_hh, (float*)p_gates, G4_, H_);

    lstm_kernel<<<NH_ / 256, 256>>>(cell, b_ih, b_hh, out);

    // predictions = h1 @ W_fc^T (bias in epilogue kernel)
    gemm_nt_tf32<false><<<dim3(V_ / 64, 1), 256>>>(
        (const float*)p_h1, W_fc, out, V_, H_);
    bias_pred_kernel<<<2048, 256>>>(b_fc, out);
}

// round 4
// speedup vs baseline: 1.4255x; 1.4255x over previous
#include <cuda_runtime.h>
#include <cuda_bf16.h>
#include <mma.h>
#include <cstdint>

using namespace nvcuda;

// Problem dims (fixed)
#define S_    128
#define N_    256
#define H_    1024
#define E_    512
#define V_    32000
#define KE_   1024
#define NH_   (N_*H_)     // 262144
#define K2_   (H_+E_+H_)  // 2560 : [ctx | emb_x | h0]
#define G4_   (4*H_)      // 4096

// Scratch (allocation-free: __device__ globals)
__device__ float g_hterm[N_];
__device__ float g_rnn_in[N_*K2_];
__device__ float g_gates[N_*G4_];
__device__ float g_h1[N_*H_];

// ---------------------------------------------------------------------------
// hterm[n] = dot(W_energy[K-1, 0:H], h0[n]) + b_energy[K-1]   (one warp per n)
// ---------------------------------------------------------------------------
__global__ void hterm_kernel(const float* __restrict__ h0,
                             const float* __restrict__ W_energy,
                             const float* __restrict__ b_energy) {
    int warp = threadIdx.x >> 5, lane = threadIdx.x & 31;
    int n = blockIdx.x * 8 + warp;
    const float4* w1 = reinterpret_cast<const float4*>(W_energy + (size_t)(KE_ - 1) * (2 * H_));
    const float4* h  = reinterpret_cast<const float4*>(h0 + (size_t)n * H_);
    float acc = 0.f;
    #pragma unroll
    for (int i = 0; i < 8; i++) {
        float4 a = h[lane + i * 32], b = w1[lane + i * 32];
        acc = fmaf(a.x, b.x, acc); acc = fmaf(a.y, b.y, acc);
        acc = fmaf(a.z, b.z, acc); acc = fmaf(a.w, b.w, acc);
    }
    #pragma unroll
    for (int o = 16; o; o >>= 1) acc += __shfl_xor_sync(0xffffffffu, acc, o);
    if (lane == 0) g_hterm[n] = acc + b_energy[KE_ - 1];
}

// ---------------------------------------------------------------------------
// Fused attention: energy (channel K-1) -> softmax over S -> ctx
// one block (256 thr) per n; ctx written straight into g_rnn_in[:, 0:H]
// ---------------------------------------------------------------------------
__global__ void attn_ctx_kernel(const float* __restrict__ enc,
                                const float* __restrict__ W_energy) {
    int n = blockIdx.x;
    int tid = threadIdx.x;
    int lane = tid & 31, warp = tid >> 5;

    __shared__ float we2[H_];
    __shared__ float e_s[S_];
    __shared__ float attn[S_];
    __shared__ float red[8];

    const float* w2 = W_energy + (size_t)(KE_ - 1) * (2 * H_) + H_;
    for (int j = tid; j < H_; j += 256) we2[j] = w2[j];
    __syncthreads();

    const float* encn = enc + (size_t)n * H_;
    float ht = g_hterm[n];
    const float4* we24 = reinterpret_cast<const float4*>(we2);

    // phase 1: energies, warp per s
    for (int s = warp; s < S_; s += 8) {
        const float4* row = reinterpret_cast<const float4*>(encn + (size_t)s * NH_);
        float acc = 0.f;
        #pragma unroll
        for (int i = 0; i < 8; i++) {
            float4 a = row[lane + i * 32], b = we24[lane + i * 32];
            acc = fmaf(a.x, b.x, acc); acc = fmaf(a.y, b.y, acc);
            acc = fmaf(a.z, b.z, acc); acc = fmaf(a.w, b.w, acc);
        }
        #pragma unroll
        for (int o = 16; o; o >>= 1) acc += __shfl_xor_sync(0xffffffffu, acc, o);
        if (lane == 0) e_s[s] = fmaxf(acc + ht, 0.f);
    }
    __syncthreads();

    // softmax over S=128
    float v = (tid < S_) ? e_s[tid] : -1e30f;
    float m = v;
    #pragma unroll
    for (int o = 16; o; o >>= 1) m = fmaxf(m, __shfl_xor_sync(0xffffffffu, m, o));
    if (lane == 0) red[warp] = m;
    __syncthreads();
    m = red[0];
    #pragma unroll
    for (int w = 1; w < 8; w++) m = fmaxf(m, red[w]);
    float wv = (tid < S_) ? expf(v - m) : 0.f;
    __syncthreads();
    float sum = wv;
    #pragma unroll
    for (int o = 16; o; o >>= 1) sum += __shfl_xor_sync(0xffffffffu, sum, o);
    if (lane == 0) red[warp] = sum;
    __syncthreads();
    sum = 0.f;
    #pragma unroll
    for (int w = 0; w < 8; w++) sum += red[w];
    if (tid < S_) attn[tid] = wv / sum;
    __syncthreads();

    // phase 2: ctx, coalesced float4 per thread (1024 = 256*4)
    int j0 = tid * 4;
    float c0 = 0.f, c1 = 0.f, c2 = 0.f, c3 = 0.f;
    for (int s = 0; s < S_; s++) {
        float a = attn[s];
        const float4 r = *reinterpret_cast<const float4*>(encn + (size_t)s * NH_ + j0);
        c0 = fmaf(a, r.x, c0); c1 = fmaf(a, r.y, c1);
        c2 = fmaf(a, r.z, c2); c3 = fmaf(a, r.w, c3);
    }
    *reinterpret_cast<float4*>(g_rnn_in + (size_t)n * K2_ + j0) = make_float4(c0, c1, c2, c3);
}

// ---------------------------------------------------------------------------
// g_rnn_in[n, H:H+E] = emb[input[n]] ; g_rnn_in[n, H+E:] = h0[n]
// ---------------------------------------------------------------------------
__global__ void fill_rest_kernel(const int* __restrict__ input,
                                 const float* __restrict__ emb,
                                 const float* __restrict__ h0) {
    int idx = blockIdx.x * 256 + threadIdx.x;     // < N_ * (E_+H_) = 393216
    int n = idx / (E_ + H_), c = idx % (E_ + H_);
    float v = (c < E_) ? emb[(size_t)input[n] * E_ + c]
                       : h0[(size_t)n * H_ + (c - E_)];
    g_rnn_in[(size_t)n * K2_ + H_ + c] = v;
}

// ---------------------------------------------------------------------------
// cp.async helpers
// ---------------------------------------------------------------------------
__device__ __forceinline__ void cpa16(void* dst, const void* src) {
    uint32_t d = (uint32_t)__cvta_generic_to_shared(dst);
    asm volatile("cp.async.cg.shared.global [%0], [%1], 16;\n" :: "r"(d), "l"(src));
}
__device__ __forceinline__ void cpa_commit() {
    asm volatile("cp.async.commit_group;\n");
}
template <int NN>
__device__ __forceinline__ void cpa_wait() {
    asm volatile("cp.async.wait_group %0;\n" :: "n"(NN));
}

// ---------------------------------------------------------------------------
// Pipelined tf32 NT GEMM: C[M, Nc] = A[M, K] * B[Nc, K]^T (+ bias per column)
// BM=128 BN=64 BK=16, 3-stage cp.async, 8 warps (4x2), warp tile 32x32.
// SPLIT: B = [Blo (k<ksplit) | Bhi]  for the fused gates GEMM.
// ---------------------------------------------------------------------------
template <bool SPLIT, bool BIAS>
__global__ void __launch_bounds__(256, 2)
gemm_tf32(const float* __restrict__ A, int lda,
          const float* __restrict__ Blo, int ldlo,
          const float* __restrict__ Bhi, int ldhi, int ksplit,
          const float* __restrict__ bias,
          float* __restrict__ C, int Nc, int K) {
    constexpr int BM = 128, BN = 64, BK = 16, ST = 3, LDP = 20;
    __shared__ float As[ST][BM * LDP];
    __shared__ float Bs[ST][BN * LDP];

    int tid = threadIdx.x, warp = tid >> 5;
    int wm = warp >> 1, wn = warp & 1;           // 4 x 2 warp grid
    int bm = blockIdx.y * BM, bn = blockIdx.x * BN;

    wmma::fragment<wmma::accumulator, 16, 16, 8, float> c[2][2];

    if (BIAS) {
        // stage bias replicated over 16 rows into As[0] (pipeline not started yet)
        float* sb = &As[0][0];
        for (int i = tid; i < 16 * BN; i += 256) sb[i] = bias[bn + (i & (BN - 1))];
        __syncthreads();
        #pragma unroll
        for (int i = 0; i < 2; i++)
            #pragma unroll
            for (int j = 0; j < 2; j++)
                wmma::load_matrix_sync(c[i][j], sb + wn * 32 + j * 16, BN,
                                       wmma::mem_row_major);
        __syncthreads();
    } else {
        #pragma unroll
        for (int i = 0; i < 2; i++)
            #pragma unroll
            for (int j = 0; j < 2; j++)
                wmma::fill_fragment(c[i][j], 0.f);
    }

    // tile loader: A = 512 float4 chunks (2/thread), B = 256 chunks (1/thread)
    auto load_tile = [&](int st, int k0) {
        #pragma unroll
        for (int i = 0; i < 2; i++) {
            int e = tid + i * 256;
            int r = e >> 2, c4 = e & 3;
            cpa16(&As[st][r * LDP + c4 * 4],
                  A + (size_t)(bm + r) * lda + k0 + c4 * 4);
        }
        {
            int r = tid >> 2, c4 = tid & 3;
            int kk = k0 + c4 * 4;
            const float* src;
            if (!SPLIT || kk < ksplit)
                src = Blo + (size_t)(bn + r) * ldlo + kk;
            else
                src = Bhi + (size_t)(bn + r) * ldhi + (kk - ksplit);
            cpa16(&Bs[st][r * LDP + c4 * 4], src);
        }
    };

    #pragma unroll
    for (int s = 0; s < ST; s++) { load_tile(s, s * BK); cpa_commit(); }

    int NC = K / BK;
    for (int ci = 0; ci < NC; ci++) {
        int st = ci % ST;
        cpa_wait<ST - 1>();
        __syncthreads();

        const float* as = &As[st][0];
        const float* bs = &Bs[st][0];
        #pragma unroll
        for (int kk = 0; kk < BK; kk += 8) {
            wmma::fragment<wmma::matrix_a, 16, 16, 8, wmma::precision::tf32, wmma::row_major> a[2];
            wmma::fragment<wmma::matrix_b, 16, 16, 8, wmma::precision::tf32, wmma::col_major> b[2];
            #pragma unroll
            for (int i = 0; i < 2; i++) {
                wmma::load_matrix_sync(a[i], as + (wm * 32 + i * 16) * LDP + kk, LDP);
                #pragma unroll
                for (int t = 0; t < a[i].num_elements; t++)
                    a[i].x[t] = wmma::__float_to_tf32(a[i].x[t]);
            }
            #pragma unroll
            for (int j = 0; j < 2; j++) {
                wmma::load_matrix_sync(b[j], bs + (wn * 32 + j * 16) * LDP + kk, LDP);
                #pragma unroll
                for (int t = 0; t < b[j].num_elements; t++)
                    b[j].x[t] = wmma::__float_to_tf32(b[j].x[t]);
            }
            #pragma unroll
            for (int i = 0; i < 2; i++)
                #pragma unroll
                for (int j = 0; j < 2; j++)
                    wmma::mma_sync(c[i][j], a[i], b[j], c[i][j]);
        }
        __syncthreads();

        int knext = (ci + ST) * BK;
        if (knext < K) load_tile(st, knext);
        cpa_commit();
    }

    #pragma unroll
    for (int i = 0; i < 2; i++)
        #pragma unroll
        for (int j = 0; j < 2; j++)
            wmma::store_matrix_sync(
                C + (size_t)(bm + wm * 32 + i * 16) * Nc + bn + wn * 32 + j * 16,
                c[i][j], Nc, wmma::mem_row_major);
}

// ---------------------------------------------------------------------------
// LSTM pointwise: gates + biases -> h1, c1 (gate order i,f,g,o)
// ---------------------------------------------------------------------------
__global__ void lstm_kernel(const float* __restrict__ cell,
                            const float* __restrict__ b_ih,
                            const float* __restrict__ b_hh,
                            float* __restrict__ out) {
    int idx = blockIdx.x * 256 + threadIdx.x;    // < N_*H_
    int n = idx >> 10, h = idx & 1023;
    const float* g = g_gates + (size_t)n * G4_;
    float xi = g[h]          + b_ih[h]          + b_hh[h];
    float xf = g[H_ + h]     + b_ih[H_ + h]     + b_hh[H_ + h];
    float xg = g[2 * H_ + h] + b_ih[2 * H_ + h] + b_hh[2 * H_ + h];
    float xo = g[3 * H_ + h] + b_ih[3 * H_ + h] + b_hh[3 * H_ + h];
    float si = 1.f / (1.f + expf(-xi));
    float sf = 1.f / (1.f + expf(-xf));
    float so = 1.f / (1.f + expf(-xo));
    float c1 = sf * cell[idx] + si * tanhf(xg);
    float h1 = so * tanhf(c1);
    g_h1[idx] = h1;
    out[(size_t)N_ * V_ + idx] = h1;
    out[(size_t)N_ * V_ + NH_ + idx] = c1;
}

// ---------------------------------------------------------------------------
extern "C" void kernel_launch(void* const* d_in, const int* in_sizes, int n_in,
                              void* d_out, int out_size) {
    const int*   input    = (const int*)d_in[0];
    const float* enc      = (const float*)d_in[1];
    const float* hidden   = (const float*)d_in[2];
    const float* cell     = (const float*)d_in[3];
    const float* emb      = (const float*)d_in[4];
    const float* W_energy = (const float*)d_in[5];
    const float* b_energy = (const float*)d_in[6];
    const float* W_ih     = (const float*)d_in[7];
    const float* b_ih     = (const float*)d_in[8];
    const float* W_hh     = (const float*)d_in[9];
    const float* b_hh     = (const float*)d_in[10];
    const float* W_fc     = (const float*)d_in[11];
    const float* b_fc     = (const float*)d_in[12];
    float* out = (float*)d_out;

    void *p_rnn = nullptr, *p_gates = nullptr, *p_h1 = nullptr;
    cudaGetSymbolAddress(&p_rnn, g_rnn_in);
    cudaGetSymbolAddress(&p_gates, g_gates);
    cudaGetSymbolAddress(&p_h1, g_h1);

    hterm_kernel<<<N_ / 8, 256>>>(hidden, W_energy, b_energy);
    attn_ctx_kernel<<<N_, 256>>>(enc, W_energy);
    fill_rest_kernel<<<(N_ * (E_ + H_)) / 256, 256>>>(input, emb, hidden);

    // gates = [ctx|emb|h0] @ [W_ih | W_hh]^T  (fused, K=2560, split at 1536)
    gemm_tf32<true, false><<<dim3(G4_ / 64, 2), 256>>>(
        (const float*)p_rnn, K2_, W_ih, H_ + E_, W_hh, H_, H_ + E_,
        nullptr, (float*)p_gates, G4_, K2_);

    lstm_kernel<<<NH_ / 256, 256>>>(cell, b_ih, b_hh, out);

    // predictions = h1 @ W_fc^T + b_fc  (bias folded into accumulator init)
    gemm_tf32<false, true><<<dim3(V_ / 64, 2), 256>>>(
        (const float*)p_h1, H_, W_fc, H_, nullptr, H_, K2_ /*unused*/,
        b_fc, out, V_, H_);
}

// round 5
// speedup vs baseline: 1.5118x; 1.0605x over previous
#include <cuda_runtime.h>
#include <cuda_bf16.h>
#include <mma.h>
#include <cstdint>

using namespace nvcuda;

// Problem dims (fixed)
#define S_    128
#define N_    256
#define H_    1024
#define E_    512
#define V_    32000
#define KE_   1024
#define NH_   (N_*H_)     // 262144
#define K2_   (H_+E_+H_)  // 2560 : [ctx | emb_x | h0]
#define G4_   (4*H_)      // 4096

// Scratch (allocation-free: __device__ globals)
__device__ float g_hterm[N_];
__device__ float g_e[S_*N_];          // energies [s][n]
__device__ float g_attn[S_*N_];       // softmax  [s][n]
__device__ float g_ctxp[4*N_*H_];     // ctx partials over 4 s-ranges
__device__ float g_rnn_in[N_*K2_];
__device__ float g_gates2[2*N_*G4_];  // split-K partials
__device__ float g_h1[N_*H_];

// ---------------------------------------------------------------------------
// hterm[n] = dot(W_energy[K-1, 0:H], h0[n]) + b_energy[K-1]   (one warp per n)
// ---------------------------------------------------------------------------
__global__ void hterm_kernel(const float* __restrict__ h0,
                             const float* __restrict__ W_energy,
                             const float* __restrict__ b_energy) {
    int warp = threadIdx.x >> 5, lane = threadIdx.x & 31;
    int n = blockIdx.x * 8 + warp;
    const float4* w1 = reinterpret_cast<const float4*>(W_energy + (size_t)(KE_ - 1) * (2 * H_));
    const float4* h  = reinterpret_cast<const float4*>(h0 + (size_t)n * H_);
    float acc = 0.f;
    #pragma unroll
    for (int i = 0; i < 8; i++) {
        float4 a = h[lane + i * 32], b = w1[lane + i * 32];
        acc = fmaf(a.x, b.x, acc); acc = fmaf(a.y, b.y, acc);
        acc = fmaf(a.z, b.z, acc); acc = fmaf(a.w, b.w, acc);
    }
    #pragma unroll
    for (int o = 16; o; o >>= 1) acc += __shfl_xor_sync(0xffffffffu, acc, o);
    if (lane == 0) g_hterm[n] = acc + b_energy[KE_ - 1];
}

// ---------------------------------------------------------------------------
// energy[s,n] = relu(hterm[n] + dot(we2, enc[s,n,:]))  — one warp per (s,n)
// grid: 4096 blocks x 256 thr = 32768 warps
// ---------------------------------------------------------------------------
__global__ void energy_kernel(const float* __restrict__ enc,
                              const float* __restrict__ W_energy) {
    int gw = blockIdx.x * 8 + (threadIdx.x >> 5);
    int lane = threadIdx.x & 31;
    int n = gw & (N_ - 1);
    int s = gw >> 8;
    const float4* row = reinterpret_cast<const float4*>(enc + (size_t)s * NH_ + (size_t)n * H_);
    const float4* w   = reinterpret_cast<const float4*>(W_energy + (size_t)(KE_ - 1) * (2 * H_) + H_);
    float acc = 0.f;
    #pragma unroll
    for (int i = 0; i < 8; i++) {
        float4 a = row[lane + i * 32], b = w[lane + i * 32];
        acc = fmaf(a.x, b.x, acc); acc = fmaf(a.y, b.y, acc);
        acc = fmaf(a.z, b.z, acc); acc = fmaf(a.w, b.w, acc);
    }
    #pragma unroll
    for (int o = 16; o; o >>= 1) acc += __shfl_xor_sync(0xffffffffu, acc, o);
    if (lane == 0) g_e[s * N_ + n] = fmaxf(acc + g_hterm[n], 0.f);
}

// ---------------------------------------------------------------------------
// softmax over s for each n — block(128) per n
// ---------------------------------------------------------------------------
__global__ void softmax_kernel() {
    int n = blockIdx.x, t = threadIdx.x;          // t = s
    int lane = t & 31, warp = t >> 5;
    __shared__ float red[4];
    float v = g_e[t * N_ + n];
    float m = v;
    #pragma unroll
    for (int o = 16; o; o >>= 1) m = fmaxf(m, __shfl_xor_sync(0xffffffffu, m, o));
    if (lane == 0) red[warp] = m;
    __syncthreads();
    m = fmaxf(fmaxf(red[0], red[1]), fmaxf(red[2], red[3]));
    float wv = expf(v - m);
    __syncthreads();
    float sum = wv;
    #pragma unroll
    for (int o = 16; o; o >>= 1) sum += __shfl_xor_sync(0xffffffffu, sum, o);
    if (lane == 0) red[warp] = sum;
    __syncthreads();
    sum = red[0] + red[1] + red[2] + red[3];
    g_attn[t * N_ + n] = wv / sum;
}

// ---------------------------------------------------------------------------
// ctx partial: block (n, q); q covers s in [32q, 32q+32). 256 thr, 4 cols each.
// ---------------------------------------------------------------------------
__global__ void ctx_kernel(const float* __restrict__ enc) {
    int n = blockIdx.x, q = blockIdx.y, tid = threadIdx.x;
    __shared__ float at[32];
    if (tid < 32) at[tid] = g_attn[(q * 32 + tid) * N_ + n];
    __syncthreads();
    int j0 = tid * 4;
    const float* encn = enc + (size_t)(q * 32) * NH_ + (size_t)n * H_ + j0;
    float c0 = 0.f, c1 = 0.f, c2 = 0.f, c3 = 0.f;
    #pragma unroll 4
    for (int s = 0; s < 32; s++) {
        float a = at[s];
        float4 r = *reinterpret_cast<const float4*>(encn + (size_t)s * NH_);
        c0 = fmaf(a, r.x, c0); c1 = fmaf(a, r.y, c1);
        c2 = fmaf(a, r.z, c2); c3 = fmaf(a, r.w, c3);
    }
    *reinterpret_cast<float4*>(g_ctxp + ((size_t)q * N_ + n) * H_ + j0) =
        make_float4(c0, c1, c2, c3);
}

// ---------------------------------------------------------------------------
// Assemble g_rnn_in[n, :] = [ctx(sum of 4 partials) | emb[input[n]] | h0[n]]
// ---------------------------------------------------------------------------
__global__ void assemble_kernel(const int* __restrict__ input,
                                const float* __restrict__ emb,
                                const float* __restrict__ h0) {
    int idx = blockIdx.x * 256 + threadIdx.x;     // < N_*K2_ = 655360
    int n = idx / K2_, c = idx % K2_;
    float v;
    if (c < H_) {
        size_t o = (size_t)n * H_ + c;
        v = g_ctxp[o] + g_ctxp[NH_ + o] + g_ctxp[2 * NH_ + o] + g_ctxp[3 * NH_ + o];
    } else if (c < H_ + E_) {
        v = emb[(size_t)input[n] * E_ + (c - H_)];
    } else {
        v = h0[(size_t)n * H_ + (c - H_ - E_)];
    }
    g_rnn_in[idx] = v;
}

// ---------------------------------------------------------------------------
// cp.async helpers
// ---------------------------------------------------------------------------
__device__ __forceinline__ void cpa16(void* dst, const void* src) {
    uint32_t d = (uint32_t)__cvta_generic_to_shared(dst);
    asm volatile("cp.async.cg.shared.global [%0], [%1], 16;\n" :: "r"(d), "l"(src));
}
__device__ __forceinline__ void cpa_commit() {
    asm volatile("cp.async.commit_group;\n");
}
template <int NN>
__device__ __forceinline__ void cpa_wait() {
    asm volatile("cp.async.wait_group %0;\n" :: "n"(NN));
}

// ---------------------------------------------------------------------------
// Pipelined tf32 NT GEMM: C[M=256, Nc] = A[M, K] * B[Nc, K]^T (+ bias)
// BM=128, BN/ST template. 8 warps 4(m)x2(n); warp tile 32 x (BN/2).
// Split-K via blockIdx.z: k range [z*klen, (z+1)*klen), C offset z*zstride.
// SPLIT: B = [Blo (k<ksplit) | Bhi]  (fused gates GEMM).
// ---------------------------------------------------------------------------
template <int BN, int ST, bool SPLIT, bool BIAS>
__global__ void __launch_bounds__(256, 2)
gemm_tf32(const float* __restrict__ A, int lda,
          const float* __restrict__ Blo, int ldlo,
          const float* __restrict__ Bhi, int ldhi, int ksplit,
          const float* __restrict__ bias,
          float* __restrict__ C, int Nc, int klen, size_t zstride) {
    constexpr int BM = 128, BK = 16, LDP = 20;
    constexpr int WNF = BN / 32;                 // n-frags per warp
    __shared__ float As[ST][BM * LDP];
    __shared__ float Bs[ST][BN * LDP];

    int tid = threadIdx.x, warp = tid >> 5;
    int wm = warp >> 1, wn = warp & 1;
    int bm = blockIdx.y * BM, bn = blockIdx.x * BN;
    int kbeg = blockIdx.z * klen;
    C += (size_t)blockIdx.z * zstride;

    wmma::fragment<wmma::accumulator, 16, 16, 8, float> c[2][WNF];

    if (BIAS) {
        float* sb = &As[0][0];
        for (int i = tid; i < 16 * BN; i += 256) sb[i] = bias[bn + (i & (BN - 1))];
        __syncthreads();
        #pragma unroll
        for (int i = 0; i < 2; i++)
            #pragma unroll
            for (int j = 0; j < WNF; j++)
                wmma::load_matrix_sync(c[i][j], sb + wn * (BN / 2) + j * 16, BN,
                                       wmma::mem_row_major);
        __syncthreads();
    } else {
        #pragma unroll
        for (int i = 0; i < 2; i++)
            #pragma unroll
            for (int j = 0; j < WNF; j++)
                wmma::fill_fragment(c[i][j], 0.f);
    }

    auto load_tile = [&](int st, int k0) {
        #pragma unroll
        for (int i = 0; i < 2; i++) {            // A: 512 f4, 2/thread
            int e = tid + i * 256;
            int r = e >> 2, c4 = e & 3;
            cpa16(&As[st][r * LDP + c4 * 4],
                  A + (size_t)(bm + r) * lda + k0 + c4 * 4);
        }
        #pragma unroll
        for (int i = 0; i < BN / 64; i++) {      // B: BN*4 f4
            int e = tid + i * 256;
            int r = e >> 2, c4 = e & 3;
            int kk = k0 + c4 * 4;
            const float* src;
            if (!SPLIT || kk < ksplit)
                src = Blo + (size_t)(bn + r) * ldlo + kk;
            else
                src = Bhi + (size_t)(bn + r) * ldhi + (kk - ksplit);
            cpa16(&Bs[st][r * LDP + c4 * 4], src);
        }
    };

    #pragma unroll
    for (int s = 0; s < ST; s++) { load_tile(s, kbeg + s * BK); cpa_commit(); }

    int NC = klen / BK;
    for (int ci = 0; ci < NC; ci++) {
        int st = ci % ST;
        cpa_wait<ST - 1>();
        __syncthreads();

        const float* as = &As[st][0];
        const float* bs = &Bs[st][0];
        #pragma unroll
        for (int kk = 0; kk < BK; kk += 8) {
            wmma::fragment<wmma::matrix_a, 16, 16, 8, wmma::precision::tf32, wmma::row_major> a[2];
            wmma::fragment<wmma::matrix_b, 16, 16, 8, wmma::precision::tf32, wmma::col_major> b[WNF];
            #pragma unroll
            for (int i = 0; i < 2; i++) {
                wmma::load_matrix_sync(a[i], as + (wm * 32 + i * 16) * LDP + kk, LDP);
                #pragma unroll
                for (int t = 0; t < a[i].num_elements; t++)
                    a[i].x[t] = wmma::__float_to_tf32(a[i].x[t]);
            }
            #pragma unroll
            for (int j = 0; j < WNF; j++) {
                wmma::load_matrix_sync(b[j], bs + (wn * (BN / 2) + j * 16) * LDP + kk, LDP);
                #pragma unroll
                for (int t = 0; t < b[j].num_elements; t++)
                    b[j].x[t] = wmma::__float_to_tf32(b[j].x[t]);
            }
            #pragma unroll
            for (int i = 0; i < 2; i++)
                #pragma unroll
                for (int j = 0; j < WNF; j++)
                    wmma::mma_sync(c[i][j], a[i], b[j], c[i][j]);
        }
        __syncthreads();

        int knext = kbeg + (ci + ST) * BK;
        if (ci + ST < NC) load_tile(st, knext);
        cpa_commit();
    }

    #pragma unroll
    for (int i = 0; i < 2; i++)
        #pragma unroll
        for (int j = 0; j < WNF; j++)
            wmma::store_matrix_sync(
                C + (size_t)(bm + wm * 32 + i * 16) * Nc + bn + wn * (BN / 2) + j * 16,
                c[i][j], Nc, wmma::mem_row_major);
}

// ---------------------------------------------------------------------------
// LSTM pointwise: sum split-K gate partials + biases -> h1, c1 (order i,f,g,o)
// ---------------------------------------------------------------------------
__global__ void lstm_kernel(const float* __restrict__ cell,
                            const float* __restrict__ b_ih,
                            const float* __restrict__ b_hh,
                            float* __restrict__ out) {
    int idx = blockIdx.x * 256 + threadIdx.x;    // < N_*H_
    int n = idx >> 10, h = idx & 1023;
    const float* gA = g_gates2 + (size_t)n * G4_;
    const float* gB = g_gates2 + (size_t)N_ * G4_ + (size_t)n * G4_;
    float xi = gA[h]          + gB[h]          + b_ih[h]          + b_hh[h];
    float xf = gA[H_ + h]     + gB[H_ + h]     + b_ih[H_ + h]     + b_hh[H_ + h];
    float xg = gA[2 * H_ + h] + gB[2 * H_ + h] + b_ih[2 * H_ + h] + b_hh[2 * H_ + h];
    float xo = gA[3 * H_ + h] + gB[3 * H_ + h] + b_ih[3 * H_ + h] + b_hh[3 * H_ + h];
    float si = 1.f / (1.f + expf(-xi));
    float sf = 1.f / (1.f + expf(-xf));
    float so = 1.f / (1.f + expf(-xo));
    float c1 = sf * cell[idx] + si * tanhf(xg);
    float h1 = so * tanhf(c1);
    g_h1[idx] = h1;
    out[(size_t)N_ * V_ + idx] = h1;
    out[(size_t)N_ * V_ + NH_ + idx] = c1;
}

// ---------------------------------------------------------------------------
extern "C" void kernel_launch(void* const* d_in, const int* in_sizes, int n_in,
                              void* d_out, int out_size) {
    const int*   input    = (const int*)d_in[0];
    const float* enc      = (const float*)d_in[1];
    const float* hidden   = (const float*)d_in[2];
    const float* cell     = (const float*)d_in[3];
    const float* emb      = (const float*)d_in[4];
    const float* W_energy = (const float*)d_in[5];
    const float* b_energy = (const float*)d_in[6];
    const float* W_ih     = (const float*)d_in[7];
    const float* b_ih     = (const float*)d_in[8];
    const float* W_hh     = (const float*)d_in[9];
    const float* b_hh     = (const float*)d_in[10];
    const float* W_fc     = (const float*)d_in[11];
    const float* b_fc     = (const float*)d_in[12];
    float* out = (float*)d_out;

    void *p_rnn = nullptr, *p_gates = nullptr, *p_h1 = nullptr;
    cudaGetSymbolAddress(&p_rnn, g_rnn_in);
    cudaGetSymbolAddress(&p_gates, g_gates2);
    cudaGetSymbolAddress(&p_h1, g_h1);

    hterm_kernel<<<N_ / 8, 256>>>(hidden, W_energy, b_energy);
    energy_kernel<<<(S_ * N_) / 8, 256>>>(enc, W_energy);
    softmax_kernel<<<N_, 128>>>();
    ctx_kernel<<<dim3(N_, 4), 256>>>(enc);
    assemble_kernel<<<(N_ * K2_) / 256, 256>>>(input, emb, hidden);

    // gates = [ctx|emb|h0] @ [W_ih | W_hh]^T ; split-K x2 (klen=1280)
    gemm_tf32<64, 3, true, false><<<dim3(G4_ / 64, 2, 2), 256>>>(
        (const float*)p_rnn, K2_, W_ih, H_ + E_, W_hh, H_, H_ + E_,
        nullptr, (float*)p_gates, G4_, K2_ / 2, (size_t)N_ * G4_);

    lstm_kernel<<<NH_ / 256, 256>>>(cell, b_ih, b_hh, out);

    // predictions = h1 @ W_fc^T + b_fc  (BN=128 tile, bias folded)
    gemm_tf32<128, 2, false, true><<<dim3(V_ / 128, 2, 1), 256>>>(
        (const float*)p_h1, H_, W_fc, H_, nullptr, H_, 0,
        b_fc, out, V_, H_, 0);
}

// round 13
// speedup vs baseline: 2.3289x; 1.5405x over previous
#include <cuda_runtime.h>
#include <cuda_fp16.h>
#include <mma.h>
#include <cstdint>

using namespace nvcuda;

// Problem dims (fixed)
#define S_    128
#define N_    256
#define H_    1024
#define E_    512
#define V_    32000
#define KE_   1024
#define NH_   (N_*H_)     // 262144
#define K2_   (H_+E_+H_)  // 2560 : [ctx | emb_x | h0]
#define G4_   (4*H_)      // 4096

// Scratch (allocation-free: __device__ globals)
__device__ float g_hterm[N_];
__device__ float g_e[S_*N_];            // energies [s][n]
__device__ float g_attn[S_*N_];         // softmax  [s][n]
__device__ float g_ctxp[4*N_*H_];       // ctx partials over 4 s-ranges
__device__ __half g_rnn_h[N_*K2_];      // A for gates GEMM (half)
__device__ __half g_h1_h[N_*H_];        // A for vocab GEMM (half)
__device__ __half g_Wg_h[(size_t)G4_*K2_];   // fused [W_ih|W_hh] half (21MB)
__device__ __half g_Wfc_h[(size_t)V_*H_];    // W_fc half (65.5MB)
__device__ float g_gates2[2*N_*G4_];    // split-K partials

// ---------------------------------------------------------------------------
// hterm[n] = dot(W_energy[K-1, 0:H], h0[n]) + b_energy[K-1]   (one warp per n)
// ---------------------------------------------------------------------------
__global__ void hterm_kernel(const float* __restrict__ h0,
                             const float* __restrict__ W_energy,
                             const float* __restrict__ b_energy) {
    int warp = threadIdx.x >> 5, lane = threadIdx.x & 31;
    int n = blockIdx.x * 8 + warp;
    const float4* w1 = reinterpret_cast<const float4*>(W_energy + (size_t)(KE_ - 1) * (2 * H_));
    const float4* h  = reinterpret_cast<const float4*>(h0 + (size_t)n * H_);
    float acc = 0.f;
    #pragma unroll
    for (int i = 0; i < 8; i++) {
        float4 a = h[lane + i * 32], b = w1[lane + i * 32];
        acc = fmaf(a.x, b.x, acc); acc = fmaf(a.y, b.y, acc);
        acc = fmaf(a.z, b.z, acc); acc = fmaf(a.w, b.w, acc);
    }
    #pragma unroll
    for (int o = 16; o; o >>= 1) acc += __shfl_xor_sync(0xffffffffu, acc, o);
    if (lane == 0) g_hterm[n] = acc + b_energy[KE_ - 1];
}

// ---------------------------------------------------------------------------
// energy[s,n] = relu(hterm[n] + dot(we2, enc[s,n,:]))  — one warp per (s,n)
// ---------------------------------------------------------------------------
__global__ void energy_kernel(const float* __restrict__ enc,
                              const float* __restrict__ W_energy) {
    int gw = blockIdx.x * 8 + (threadIdx.x >> 5);
    int lane = threadIdx.x & 31;
    int n = gw & (N_ - 1);
    int s = gw >> 8;
    const float4* row = reinterpret_cast<const float4*>(enc + (size_t)s * NH_ + (size_t)n * H_);
    const float4* w   = reinterpret_cast<const float4*>(W_energy + (size_t)(KE_ - 1) * (2 * H_) + H_);
    float acc = 0.f;
    #pragma unroll
    for (int i = 0; i < 8; i++) {
        float4 a = row[lane + i * 32], b = w[lane + i * 32];
        acc = fmaf(a.x, b.x, acc); acc = fmaf(a.y, b.y, acc);
        acc = fmaf(a.z, b.z, acc); acc = fmaf(a.w, b.w, acc);
    }
    #pragma unroll
    for (int o = 16; o; o >>= 1) acc += __shfl_xor_sync(0xffffffffu, acc, o);
    if (lane == 0) g_e[s * N_ + n] = fmaxf(acc + g_hterm[n], 0.f);
}

// ---------------------------------------------------------------------------
// softmax over s for each n — block(128) per n
// ---------------------------------------------------------------------------
__global__ void softmax_kernel() {
    int n = blockIdx.x, t = threadIdx.x;          // t = s
    int lane = t & 31, warp = t >> 5;
    __shared__ float red[4];
    float v = g_e[t * N_ + n];
    float m = v;
    #pragma unroll
    for (int o = 16; o; o >>= 1) m = fmaxf(m, __shfl_xor_sync(0xffffffffu, m, o));
    if (lane == 0) red[warp] = m;
    __syncthreads();
    m = fmaxf(fmaxf(red[0], red[1]), fmaxf(red[2], red[3]));
    float wv = expf(v - m);
    __syncthreads();
    float sum = wv;
    #pragma unroll
    for (int o = 16; o; o >>= 1) sum += __shfl_xor_sync(0xffffffffu, sum, o);
    if (lane == 0) red[warp] = sum;
    __syncthreads();
    sum = red[0] + red[1] + red[2] + red[3];
    g_attn[t * N_ + n] = wv / sum;
}

// ---------------------------------------------------------------------------
// ctx partial: block (n, q); q covers s in [32q, 32q+32). 256 thr, 4 cols each.
// ---------------------------------------------------------------------------
__global__ void ctx_kernel(const float* __restrict__ enc) {
    int n = blockIdx.x, q = blockIdx.y, tid = threadIdx.x;
    __shared__ float at[32];
    if (tid < 32) at[tid] = g_attn[(q * 32 + tid) * N_ + n];
    __syncthreads();
    int j0 = tid * 4;
    const float* encn = enc + (size_t)(q * 32) * NH_ + (size_t)n * H_ + j0;
    float c0 = 0.f, c1 = 0.f, c2 = 0.f, c3 = 0.f;
    #pragma unroll 4
    for (int s = 0; s < 32; s++) {
        float a = at[s];
        float4 r = *reinterpret_cast<const float4*>(encn + (size_t)s * NH_);
        c0 = fmaf(a, r.x, c0); c1 = fmaf(a, r.y, c1);
        c2 = fmaf(a, r.z, c2); c3 = fmaf(a, r.w, c3);
    }
    *reinterpret_cast<float4*>(g_ctxp + ((size_t)q * N_ + n) * H_ + j0) =
        make_float4(c0, c1, c2, c3);
}

// ---------------------------------------------------------------------------
// Assemble g_rnn_h[n,:] = half([ctx(sum of 4 partials) | emb[input[n]] | h0[n]])
// ---------------------------------------------------------------------------
__global__ void assemble_kernel(const int* __restrict__ input,
                                const float* __restrict__ emb,
                                const float* __restrict__ h0) {
    int idx = blockIdx.x * 256 + threadIdx.x;     // < N_*K2_
    int n = idx / K2_, c = idx % K2_;
    float v;
    if (c < H_) {
        size_t o = (size_t)n * H_ + c;
        v = g_ctxp[o] + g_ctxp[NH_ + o] + g_ctxp[2 * NH_ + o] + g_ctxp[3 * NH_ + o];
    } else if (c < H_ + E_) {
        v = emb[(size_t)input[n] * E_ + (c - H_)];
    } else {
        v = h0[(size_t)n * H_ + (c - H_ - E_)];
    }
    g_rnn_h[idx] = __float2half_rn(v);
}

// ---------------------------------------------------------------------------
// Weight converts: fp32 -> half (4 elems/thread, vectorized)
// ---------------------------------------------------------------------------
__global__ void conv_wg_kernel(const float* __restrict__ W_ih,
                               const float* __restrict__ W_hh) {
    size_t idx = ((size_t)blockIdx.x * 256 + threadIdx.x) * 4;   // < 4096*2560
    int row = (int)(idx / K2_), col = (int)(idx % K2_);
    const float* src = (col < H_ + E_)
        ? W_ih + (size_t)row * (H_ + E_) + col
        : W_hh + (size_t)row * H_ + (col - (H_ + E_));
    float4 v = *reinterpret_cast<const float4*>(src);
    __half2* dst = reinterpret_cast<__half2*>(g_Wg_h + idx);
    dst[0] = __floats2half2_rn(v.x, v.y);
    dst[1] = __floats2half2_rn(v.z, v.w);
}

__global__ void conv_wfc_kernel(const float* __restrict__ W_fc) {
    size_t idx = ((size_t)blockIdx.x * 256 + threadIdx.x) * 4;   // < 32000*1024
    float4 v = *reinterpret_cast<const float4*>(W_fc + idx);
    __half2* dst = reinterpret_cast<__half2*>(g_Wfc_h + idx);
    dst[0] = __floats2half2_rn(v.x, v.y);
    dst[1] = __floats2half2_rn(v.z, v.w);
}

// ---------------------------------------------------------------------------
// cp.async helpers
// ---------------------------------------------------------------------------
__device__ __forceinline__ void cpa16(void* dst, const void* src) {
    uint32_t d = (uint32_t)__cvta_generic_to_shared(dst);
    asm volatile("cp.async.cg.shared.global [%0], [%1], 16;\n" :: "r"(d), "l"(src));
}
__device__ __forceinline__ void cpa_commit() {
    asm volatile("cp.async.commit_group;\n");
}
template <int NN>
__device__ __forceinline__ void cpa_wait() {
    asm volatile("cp.async.wait_group %0;\n" :: "n"(NN));
}

// ---------------------------------------------------------------------------
// Pipelined fp16 NT GEMM, fp32 accumulate: C[M=256, Nc] = A*B^T (+bias)
// BM=128 BN=64 BK=32, 3-stage cp.async, 8 warps 4(m)x2(n), warp tile 32x32.
// Split-K via blockIdx.z (gates): k in [z*klen,(z+1)*klen), C += z*zstride.
// ---------------------------------------------------------------------------
template <bool BIAS>
__global__ void __launch_bounds__(256, 2)
gemm_fp16(const __half* __restrict__ A, int lda,
          const __half* __restrict__ B, int ldb,
          const float* __restrict__ bias,
          float* __restrict__ C, int Nc, int klen, size_t zstride) {
    constexpr int BM = 128, BN = 64, BK = 32, ST = 3, LDH = 40;  // halves
    __shared__ __half As[ST][BM * LDH];   // 3*128*40*2 = 30720 B
    __shared__ __half Bs[ST][BN * LDH];   // 3*64*40*2  = 15360 B

    int tid = threadIdx.x, warp = tid >> 5;
    int wm = warp >> 1, wn = warp & 1;
    int bm = blockIdx.y * BM, bn = blockIdx.x * BN;
    int kbeg = blockIdx.z * klen;
    C += (size_t)blockIdx.z * zstride;

    wmma::fragment<wmma::accumulator, 16, 16, 16, float> c[2][2];

    if (BIAS) {
        // stage bias replicated 16 rows in As[0] (as float), before pipeline
        float* sb = reinterpret_cast<float*>(&As[0][0]);   // 4KB < 10240B stage
        for (int i = tid; i < 16 * BN; i += 256) sb[i] = bias[bn + (i & (BN - 1))];
        __syncthreads();
        #pragma unroll
        for (int i = 0; i < 2; i++)
            #pragma unroll
            for (int j = 0; j < 2; j++)
                wmma::load_matrix_sync(c[i][j], sb + wn * 32 + j * 16, BN,
                                       wmma::mem_row_major);
        __syncthreads();
    } else {
        #pragma unroll
        for (int i = 0; i < 2; i++)
            #pragma unroll
            for (int j = 0; j < 2; j++)
                wmma::fill_fragment(c[i][j], 0.f);
    }

    // A tile: 128x32 halves = 8192B = 512 x 16B (2/thread); B: 256 x 16B (1/thread)
    auto load_tile = [&](int st, int k0) {
        #pragma unroll
        for (int i = 0; i < 2; i++) {
            int e = tid + i * 256;
            int r = e >> 2, c8 = e & 3;
            cpa16(&As[st][r * LDH + c8 * 8],
                  A + (size_t)(bm + r) * lda + k0 + c8 * 8);
        }
        {
            int r = tid >> 2, c8 = tid & 3;
            cpa16(&Bs[st][r * LDH + c8 * 8],
                  B + (size_t)(bn + r) * ldb + k0 + c8 * 8);
        }
    };

    #pragma unroll
    for (int s = 0; s < ST; s++) { load_tile(s, kbeg + s * BK); cpa_commit(); }

    int NC = klen / BK;
    for (int ci = 0; ci < NC; ci++) {
        int st = ci % ST;
        cpa_wait<ST - 1>();
        __syncthreads();

        const __half* as = &As[st][0];
        const __half* bs = &Bs[st][0];
        #pragma unroll
        for (int kk = 0; kk < BK; kk += 16) {
            wmma::fragment<wmma::matrix_a, 16, 16, 16, __half, wmma::row_major> a[2];
            wmma::fragment<wmma::matrix_b, 16, 16, 16, __half, wmma::col_major> b[2];
            #pragma unroll
            for (int i = 0; i < 2; i++)
                wmma::load_matrix_sync(a[i], as + (wm * 32 + i * 16) * LDH + kk, LDH);
            #pragma unroll
            for (int j = 0; j < 2; j++)
                wmma::load_matrix_sync(b[j], bs + (wn * 32 + j * 16) * LDH + kk, LDH);
            #pragma unroll
            for (int i = 0; i < 2; i++)
                #pragma unroll
                for (int j = 0; j < 2; j++)
                    wmma::mma_sync(c[i][j], a[i], b[j], c[i][j]);
        }
        __syncthreads();

        if (ci + ST < NC) load_tile(st, kbeg + (ci + ST) * BK);
        cpa_commit();
    }

    #pragma unroll
    for (int i = 0; i < 2; i++)
        #pragma unroll
        for (int j = 0; j < 2; j++)
            wmma::store_matrix_sync(
                C + (size_t)(bm + wm * 32 + i * 16) * Nc + bn + wn * 32 + j * 16,
                c[i][j], Nc, wmma::mem_row_major);
}

// ---------------------------------------------------------------------------
// LSTM pointwise: sum split-K gate partials + biases -> h1, c1 (order i,f,g,o)
// ---------------------------------------------------------------------------
__global__ void lstm_kernel(const float* __restrict__ cell,
                            const float* __restrict__ b_ih,
                            const float* __restrict__ b_hh,
                            float* __restrict__ out) {
    int idx = blockIdx.x * 256 + threadIdx.x;    // < N_*H_
    int n = idx >> 10, h = idx & 1023;
    const float* gA = g_gates2 + (size_t)n * G4_;
    const float* gB = g_gates2 + (size_t)N_ * G4_ + (size_t)n * G4_;
    float xi = gA[h]          + gB[h]          + b_ih[h]          + b_hh[h];
    float xf = gA[H_ + h]     + gB[H_ + h]     + b_ih[H_ + h]     + b_hh[H_ + h];
    float xg = gA[2 * H_ + h] + gB[2 * H_ + h] + b_ih[2 * H_ + h] + b_hh[2 * H_ + h];
    float xo = gA[3 * H_ + h] + gB[3 * H_ + h] + b_ih[3 * H_ + h] + b_hh[3 * H_ + h];
    float si = 1.f / (1.f + expf(-xi));
    float sf = 1.f / (1.f + expf(-xf));
    float so = 1.f / (1.f + expf(-xo));
    float c1 = sf * cell[idx] + si * tanhf(xg);
    float h1 = so * tanhf(c1);
    g_h1_h[idx] = __float2half_rn(h1);
    out[(size_t)N_ * V_ + idx] = h1;
    out[(size_t)N_ * V_ + NH_ + idx] = c1;
}

// ---------------------------------------------------------------------------
extern "C" void kernel_launch(void* const* d_in, const int* in_sizes, int n_in,
                              void* d_out, int out_size) {
    const int*   input    = (const int*)d_in[0];
    const float* enc      = (const float*)d_in[1];
    const float* hidden   = (const float*)d_in[2];
    const float* cell     = (const float*)d_in[3];
    const float* emb      = (const float*)d_in[4];
    const float* W_energy = (const float*)d_in[5];
    const float* b_energy = (const float*)d_in[6];
    const float* W_ih     = (const float*)d_in[7];
    const float* b_ih     = (const float*)d_in[8];
    const float* W_hh     = (const float*)d_in[9];
    const float* b_hh     = (const float*)d_in[10];
    const float* W_fc     = (const float*)d_in[11];
    const float* b_fc     = (const float*)d_in[12];
    float* out = (float*)d_out;

    void *p_rnn = nullptr, *p_gates = nullptr, *p_h1 = nullptr, *p_wg = nullptr, *p_wfc = nullptr;
    cudaGetSymbolAddress(&p_rnn, g_rnn_h);
    cudaGetSymbolAddress(&p_gates, g_gates2);
    cudaGetSymbolAddress(&p_h1, g_h1_h);
    cudaGetSymbolAddress(&p_wg, g_Wg_h);
    cudaGetSymbolAddress(&p_wfc, g_Wfc_h);

    // weight converts (independent of attention path)
    conv_wfc_kernel<<<((size_t)V_ * H_ / 4) / 256, 256>>>(W_fc);
    conv_wg_kernel<<<((size_t)G4_ * K2_ / 4) / 256, 256>>>(W_ih, W_hh);

    hterm_kernel<<<N_ / 8, 256>>>(hidden, W_energy, b_energy);
    energy_kernel<<<(S_ * N_) / 8, 256>>>(enc, W_energy);
    softmax_kernel<<<N_, 128>>>();
    ctx_kernel<<<dim3(N_, 4), 256>>>(enc);
    assemble_kernel<<<(N_ * K2_) / 256, 256>>>(input, emb, hidden);

    // gates = [ctx|emb|h0] @ Wg^T ; split-K x2 (klen=1280)
    gemm_fp16<false><<<dim3(G4_ / 64, 2, 2), 256>>>(
        (const __half*)p_rnn, K2_, (const __half*)p_wg, K2_,
        nullptr, (float*)p_gates, G4_, K2_ / 2, (size_t)N_ * G4_);

    lstm_kernel<<<NH_ / 256, 256>>>(cell, b_ih, b_hh, out);

    // predictions = h1 @ W_fc^T + b_fc (bias folded)
    gemm_fp16<true><<<dim3(V_ / 64, 2, 1), 256>>>(
        (const __half*)p_h1, H_, (const __half*)p_wfc, H_,
        b_fc, out, V_, H_, 0);
}